// round 3
// baseline (speedup 1.0000x reference)
#include <cuda_runtime.h>
#include <cstdint>

// Problem constants
#define NT   9
#define NPIX 65536          // 256*256
#define NB   16

typedef unsigned long long ull;

// ---------------------------------------------------------------------------
// Packed f32x2 helpers (Blackwell: fma.rn.f32x2 via PTX only)
// ---------------------------------------------------------------------------
__device__ __forceinline__ ull pack2(float a, float b) {
    ull r;
    asm("mov.b64 %0, {%1,%2};" : "=l"(r) : "f"(a), "f"(b));
    return r;
}
__device__ __forceinline__ void unpack2(ull v, float& a, float& b) {
    asm("mov.b64 {%0,%1}, %2;" : "=f"(a), "=f"(b) : "l"(v));
}
__device__ __forceinline__ void fma2(ull& acc, ull v, ull w) {
    asm("fma.rn.f32x2 %0, %1, %2, %3;" : "=l"(acc) : "l"(v), "l"(w), "l"(acc));
}

__device__ __forceinline__ float sp10(float x) {
    // softplus(10x)/10 = max(x,0) + log1p(exp(-|10x|))/10
    float z = 10.0f * x;
    return fmaxf(x, 0.0f) + 0.1f * log1pf(expf(-fabsf(z)));
}

// ---------------------------------------------------------------------------
// Scratch (device globals — allocation-free)
// ---------------------------------------------------------------------------
__device__ float g_p1[(size_t)NB * 10 * NPIX];
__device__ float g_p2[(size_t)NB * 20 * NPIX];
__device__ float g_p3[(size_t)NB * 54 * NPIX];
__device__ float g_XG [(size_t)NB * NT * NPIX];
__device__ float g_KG [(size_t)NB * NT * NPIX];
__device__ float g_M1 [(size_t)NB * NT * NPIX];
__device__ float g_M2 [(size_t)NB * NT * NPIX];
__device__ float g_H11[(size_t)NB * NT * NPIX];
__device__ float g_HB [(size_t)NB * NT * NPIX];
__device__ float g_H22[(size_t)NB * NT * NPIX];
__device__ float g_W  [(size_t)NB * NT * NPIX];
__device__ float g_part[NB * NT * 64];   // block partials for x_out

// ---------------------------------------------------------------------------
// Direct 3x3 SAME conv, NCHW/OIHW, zero pad.
// Block = (32,4) threads, tile = 32(x) x 8(y); each thread: 2 rows x COUT outs.
// Accumulators packed as (co even, co odd) f32x2; weights read as LDS.64
// broadcast from smem (pairs contiguous); value broadcast packed once per tap.
// ---------------------------------------------------------------------------
template <int CIN, int COUT, int CCH, bool RELU>
__device__ __forceinline__ void conv_body(const float* __restrict__ in,
                                          const float* __restrict__ wt,
                                          float* __restrict__ out) {
    __shared__ __align__(16) float s_w[CIN * 9 * COUT];
    __shared__ float s_in[CCH][10][34];

    const int b  = blockIdx.z;
    const int x0 = blockIdx.x * 32;
    const int y0 = blockIdx.y * 8;
    const int tx = threadIdx.x;           // 0..31
    const int ty = threadIdx.y;           // 0..3
    const int tid = ty * 32 + tx;

    // weights: s_w[(ci*9+tap)*COUT + co] = wt[(co*CIN+ci)*9 + tap]
    for (int i = tid; i < CIN * 9 * COUT; i += 128) {
        int co = i % COUT;
        int r  = i / COUT;
        int ci = r / 9, tap = r % 9;
        s_w[i] = wt[(co * CIN + ci) * 9 + tap];
    }

    ull acc[2][COUT / 2];
#pragma unroll
    for (int k = 0; k < 2; k++)
#pragma unroll
        for (int j = 0; j < COUT / 2; j++) acc[k][j] = 0ull;

    const float* inb = in + (size_t)b * CIN * NPIX;

    for (int c0 = 0; c0 < CIN; c0 += CCH) {
        __syncthreads();
        for (int i = tid; i < CCH * 340; i += 128) {
            int ci = i / 340;
            int rr = (i / 34) % 10;
            int cc = i % 34;
            int gy = y0 + rr - 1, gx = x0 + cc - 1;
            float v = 0.0f;
            if ((unsigned)gy < 256u && (unsigned)gx < 256u) {
                v = inb[(size_t)(c0 + ci) * NPIX + gy * 256 + gx];
                if (RELU) v = fmaxf(v, 0.0f);
            }
            s_in[ci][rr][cc] = v;
        }
        __syncthreads();

#pragma unroll 1
        for (int cl = 0; cl < CCH; ++cl) {
            float v[4][3];
#pragma unroll
            for (int r = 0; r < 4; r++)
#pragma unroll
                for (int c = 0; c < 3; c++)
                    v[r][c] = s_in[cl][ty * 2 + r][tx + c];

            const float* wp = s_w + (size_t)(c0 + cl) * 9 * COUT;
#pragma unroll
            for (int ky = 0; ky < 3; ky++)
#pragma unroll
                for (int kx = 0; kx < 3; kx++) {
                    ull v0 = pack2(v[ky][kx],     v[ky][kx]);
                    ull v1 = pack2(v[ky + 1][kx], v[ky + 1][kx]);
                    const ull* w2 = (const ull*)(wp + (ky * 3 + kx) * COUT);
#pragma unroll
                    for (int j = 0; j < COUT / 2; j++) {
                        ull w = w2[j];
                        fma2(acc[0][j], v0, w);
                        fma2(acc[1][j], v1, w);
                    }
                }
        }
    }

    float* outb = out + (size_t)b * COUT * NPIX;
    const int y = y0 + ty * 2, x = x0 + tx;
#pragma unroll
    for (int j = 0; j < COUT / 2; j++) {
        float a, bb;
        unpack2(acc[0][j], a, bb);
        outb[(size_t)(2 * j)     * NPIX + y * 256 + x] = a;
        outb[(size_t)(2 * j + 1) * NPIX + y * 256 + x] = bb;
        unpack2(acc[1][j], a, bb);
        outb[(size_t)(2 * j)     * NPIX + (y + 1) * 256 + x] = a;
        outb[(size_t)(2 * j + 1) * NPIX + (y + 1) * 256 + x] = bb;
    }
}

__global__ void __launch_bounds__(128) k_conv1(const float* __restrict__ x,
                                               const float* __restrict__ w) {
    conv_body<9, 10, 9, true>(x, w, g_p1);
}
__global__ void __launch_bounds__(128) k_conv2(const float* __restrict__ w) {
    conv_body<10, 20, 10, true>(g_p1, w, g_p2);
}
__global__ void __launch_bounds__(128) k_conv3(const float* __restrict__ w) {
    conv_body<20, 54, 5, false>(g_p2, w, g_p3);
}

// ---------------------------------------------------------------------------
// kappa_r / m_r outputs + KG/M1/M2 grids.
// Grids use the reference's raw-reshape reinterpretation: value at grid
// (b,t,a,c) is flat_channel_block[(a*256+c)*9 + t].
// ---------------------------------------------------------------------------
__global__ void __launch_bounds__(256) k_build_kgm(float* __restrict__ out_kap,
                                                   float* __restrict__ out_m) {
    int g = blockIdx.x * 256 + threadIdx.x;        // 0 .. NB*NPIX-1
    int b = g >> 16;
    int n = g & 65535;
    const float* pb = g_p3 + (size_t)b * 54 * NPIX;
    size_t off = (size_t)n * 9;

    float* ko = out_kap + (size_t)b * (9 * NPIX) + off;
    float* mo = out_m   + (size_t)b * (18 * NPIX) + off;
    size_t gbase = (size_t)b * NT * NPIX + n;

#pragma unroll
    for (int t = 0; t < 9; t++) {                  // channels 0..8 -> kappa
        float s = sp10(pb[off + t]);
        ko[t] = s;
        g_KG[gbase + (size_t)t * NPIX] = s;
    }
#pragma unroll
    for (int t = 0; t < 9; t++) {                  // channels 9..17 -> m1
        float v = pb[(size_t)9 * NPIX + off + t];
        mo[t] = v;
        g_M1[gbase + (size_t)t * NPIX] = v;
    }
#pragma unroll
    for (int t = 0; t < 9; t++) {                  // channels 18..26 -> m2
        float v = pb[(size_t)18 * NPIX + off + t];
        mo[(size_t)9 * NPIX + t] = v;
        g_M2[gbase + (size_t)t * NPIX] = v;
    }
}

// ---------------------------------------------------------------------------
// H_r output + H11 / (h12+h21) / H22 grids (spatially aligned with p).
// H_r[b,i,j,n,t] = delta_ij*softplus10(gamma) + v_i*v_j at (channel t, pixel n)
// ---------------------------------------------------------------------------
__global__ void __launch_bounds__(256) k_build_H(float* __restrict__ out_H) {
    int g = blockIdx.x * 256 + threadIdx.x;
    int b = g >> 16;
    int n = g & 65535;
    const float* pb = g_p3 + (size_t)b * 54 * NPIX;

    float* h00 = out_H + ((size_t)(b * 4 + 0) * NPIX + n) * 9;
    float* h01 = out_H + ((size_t)(b * 4 + 1) * NPIX + n) * 9;
    float* h10 = out_H + ((size_t)(b * 4 + 2) * NPIX + n) * 9;
    float* h11o= out_H + ((size_t)(b * 4 + 3) * NPIX + n) * 9;

    size_t gbase = (size_t)b * NT * NPIX + n;
#pragma unroll
    for (int t = 0; t < 9; t++) {
        float gg = sp10(pb[(size_t)(27 + t) * NPIX + n]);
        float vx = pb[(size_t)(36 + t) * NPIX + n];
        float vy = pb[(size_t)(45 + t) * NPIX + n];
        float a  = gg + vx * vx;
        float cd = vx * vy;
        float d2 = gg + vy * vy;
        h00[t] = a; h01[t] = cd; h10[t] = cd; h11o[t] = d2;
        size_t gi = gbase + (size_t)t * NPIX;
        g_H11[gi] = a;
        g_HB [gi] = 2.0f * cd;
        g_H22[gi] = d2;
    }
}

// ---------------------------------------------------------------------------
// XG[b,t,a,c] = x[b,t,c,a]  (per-plane 256x256 transpose)
// ---------------------------------------------------------------------------
__global__ void __launch_bounds__(256) k_transpose(const float* __restrict__ x) {
    __shared__ float s[32][33];
    int plane = blockIdx.z;                        // b*9 + t
    const float* in = x + (size_t)plane * NPIX;
    float* out = g_XG + (size_t)plane * NPIX;
    int x0 = blockIdx.x * 32, y0 = blockIdx.y * 32;
    int tx = threadIdx.x, ty = threadIdx.y;        // (32,8)
#pragma unroll
    for (int k = 0; k < 4; k++)
        s[ty + 8 * k][tx] = in[(size_t)(y0 + ty + 8 * k) * 256 + x0 + tx];
    __syncthreads();
#pragma unroll
    for (int k = 0; k < 4; k++)
        out[(size_t)(x0 + ty + 8 * k) * 256 + y0 + tx] = s[tx][ty + 8 * k];
}

// ---------------------------------------------------------------------------
// M(u) = u + A(u); A = kap^2 u + m1*dx + m2*dy - (h11*dxx + hb*dxy + h22*dyy)
// dx/dxx along 'a' (dim -2), dy/dyy along 'c' (dim -1), zero-padded boundary.
// ---------------------------------------------------------------------------
__device__ __forceinline__ float M_val(const float su[34][36], int ty, int tx,
                                       size_t idx) {
    float u  = su[ty + 1][tx + 1];
    float xp = su[ty + 2][tx + 1], xm = su[ty][tx + 1];
    float yp = su[ty + 1][tx + 2], ym = su[ty + 1][tx];
    float pp = su[ty + 2][tx + 2], pm = su[ty + 2][tx];
    float mp = su[ty][tx + 2],     mm = su[ty][tx];
    float kap = g_KG[idx], m1 = g_M1[idx], m2 = g_M2[idx];
    float h11 = g_H11[idx], hb = g_HB[idx], h22 = g_H22[idx];
    float A = kap * kap * u
            + m1 * 0.5f * (xp - xm)
            + m2 * 0.5f * (yp - ym)
            - (h11 * (xp - 2.0f * u + xm)
               + hb * 0.25f * ((pp - pm) - (mp - mm))
               + h22 * (yp - 2.0f * u + ym));
    return u + A;
}

__device__ __forceinline__ void load_tile(float su[34][36],
                                          const float* __restrict__ plane_ptr,
                                          int a0, int c0, int tid) {
    for (int i = tid; i < 34 * 34; i += 1024) {
        int r = i / 34, cc = i % 34;
        int ga = a0 + r - 1, gc = c0 + cc - 1;
        su[r][cc] = ((unsigned)ga < 256u && (unsigned)gc < 256u)
                        ? plane_ptr[(size_t)ga * 256 + gc] : 0.0f;
    }
}

__global__ void __launch_bounds__(1024) k_applyW() {
    __shared__ float su[34][36];
    int plane = blockIdx.z;
    int a0 = blockIdx.y * 32, c0 = blockIdx.x * 32;
    int tx = threadIdx.x, ty = threadIdx.y;
    int tid = ty * 32 + tx;
    load_tile(su, g_XG + (size_t)plane * NPIX, a0, c0, tid);
    __syncthreads();
    size_t idx = (size_t)plane * NPIX + (size_t)(a0 + ty) * 256 + (c0 + tx);
    g_W[idx] = M_val(su, ty, tx, idx);
}

__global__ void __launch_bounds__(1024) k_applyV() {
    __shared__ float su[34][36];
    __shared__ float red[32];
    int plane = blockIdx.z;
    int b = plane / NT, t = plane - b * NT;
    int a0 = blockIdx.y * 32, c0 = blockIdx.x * 32;
    int tx = threadIdx.x, ty = threadIdx.y;
    int tid = ty * 32 + tx;
    load_tile(su, g_W + (size_t)plane * NPIX, a0, c0, tid);
    __syncthreads();
    size_t idx = (size_t)plane * NPIX + (size_t)(a0 + ty) * 256 + (c0 + tx);
    float v  = M_val(su, ty, tx, idx);
    float xg = g_XG[idx];
    // qx[t] terms: v_t (+xg for interior t) - w_{t+1} (t<8) - w_{t-1} (t>0)
    float q = v;
    if (t >= 1 && t <= 7) q += xg;
    if (t < 8)  q -= g_W[idx + NPIX];
    if (t >= 1) q -= g_W[idx - NPIX];
    float part = xg * q;

#pragma unroll
    for (int o = 16; o > 0; o >>= 1)
        part += __shfl_down_sync(0xffffffffu, part, o);
    if ((tid & 31) == 0) red[tid >> 5] = part;
    __syncthreads();
    if (tid < 32) {
        float vs = red[tid];
#pragma unroll
        for (int o = 16; o > 0; o >>= 1)
            vs += __shfl_down_sync(0xffffffffu, vs, o);
        if (tid == 0)
            g_part[plane * 64 + blockIdx.y * 8 + blockIdx.x] = vs;
    }
}

// Deterministic per-batch final reduction of 576 block partials.
__global__ void __launch_bounds__(256) k_final(float* __restrict__ out_x) {
    __shared__ float s[256];
    int b = blockIdx.x, tid = threadIdx.x;
    float v = 0.0f;
    for (int i = tid; i < 576; i += 256) v += g_part[b * 576 + i];
    s[tid] = v;
    __syncthreads();
#pragma unroll
    for (int o = 128; o > 0; o >>= 1) {
        if (tid < o) s[tid] += s[tid + o];
        __syncthreads();
    }
    if (tid == 0) out_x[b] = s[0];
}

// ---------------------------------------------------------------------------
// Launch. Output layout: [x_out(16)] [kappa_r(16*9*65536)] [m_r(16*18*65536)]
//                        [H_r(16*4*65536*9)]
// ---------------------------------------------------------------------------
extern "C" void kernel_launch(void* const* d_in, const int* in_sizes, int n_in,
                              void* d_out, int out_size) {
    (void)in_sizes; (void)n_in; (void)out_size;
    const float* x  = (const float*)d_in[0];
    const float* w1 = (const float*)d_in[4];
    const float* w2 = (const float*)d_in[5];
    const float* w3 = (const float*)d_in[6];

    float* out     = (float*)d_out;
    float* out_kap = out + 16;
    float* out_m   = out + 16 + (size_t)NB * 9 * NPIX;              // 9437200
    float* out_H   = out + 16 + (size_t)NB * 9 * NPIX
                         + (size_t)NB * 18 * NPIX;                  // 28311568

    dim3 cb(32, 4);
    dim3 cg(8, 32, NB);
    k_conv1<<<cg, cb>>>(x, w1);
    k_conv2<<<cg, cb>>>(w2);
    k_conv3<<<cg, cb>>>(w3);

    k_build_kgm<<<4096, 256>>>(out_kap, out_m);
    k_build_H  <<<4096, 256>>>(out_H);
    k_transpose<<<dim3(8, 8, NB * NT), dim3(32, 8)>>>(x);

    k_applyW<<<dim3(8, 8, NB * NT), dim3(32, 32)>>>();
    k_applyV<<<dim3(8, 8, NB * NT), dim3(32, 32)>>>();
    k_final <<<NB, 256>>>(out);
}

// round 6
// speedup vs baseline: 1.2993x; 1.2993x over previous
#include <cuda_runtime.h>
#include <cstdint>

#define NT   9
#define NPIX 65536
#define NB   16

typedef unsigned long long ull;

// ---------------------------------------------------------------------------
// Packed f32x2 helpers (Blackwell fma.rn.f32x2, PTX-only)
// ---------------------------------------------------------------------------
__device__ __forceinline__ ull pack2(float a, float b) {
    ull r;
    asm("mov.b64 %0, {%1,%2};" : "=l"(r) : "f"(a), "f"(b));
    return r;
}
__device__ __forceinline__ void unpack2(ull v, float& a, float& b) {
    asm("mov.b64 {%0,%1}, %2;" : "=f"(a), "=f"(b) : "l"(v));
}
__device__ __forceinline__ void fma2(ull& acc, ull v, ull w) {
    asm("fma.rn.f32x2 %0, %1, %2, %3;" : "=l"(acc) : "l"(v), "l"(w), "l"(acc));
}

__device__ __forceinline__ float sp10(float x) {
    float z = 10.0f * x;
    return fmaxf(x, 0.0f) + 0.1f * log1pf(expf(-fabsf(z)));
}

// ---------------------------------------------------------------------------
// Scratch (device globals — allocation-free)
// ---------------------------------------------------------------------------
__device__ float g_p1[(size_t)NB * 10 * NPIX];
__device__ float g_p2[(size_t)NB * 20 * NPIX];
__device__ float g_p3[(size_t)NB * 54 * NPIX];
__device__ float g_KG [(size_t)NB * NT * NPIX];
__device__ float g_M1 [(size_t)NB * NT * NPIX];
__device__ float g_M2 [(size_t)NB * NT * NPIX];
__device__ float g_H11[(size_t)NB * NT * NPIX];
__device__ float g_HB [(size_t)NB * NT * NPIX];
__device__ float g_H22[(size_t)NB * NT * NPIX];
__device__ float g_part[NB * 64];

// ---------------------------------------------------------------------------
// Direct 3x3 SAME conv, NCHW/OIHW, zero pad.
// Block (32,4); tile 32 x (4*ROWS); ROWS rows per thread.
// Output-channel-pair accumulators in f32x2; weights via broadcast LDS.64.
// ---------------------------------------------------------------------------
template <int CIN, int COUT, int CCH, int ROWS, bool RELU>
__device__ __forceinline__ void conv_body(const float* __restrict__ in,
                                          const float* __restrict__ wt,
                                          float* __restrict__ out) {
    constexpr int TH = 4 * ROWS;          // tile height
    constexpr int HR = TH + 2;            // halo rows
    __shared__ __align__(16) float s_w[CIN * 9 * COUT];
    __shared__ float s_in[CCH][HR][34];

    const int b  = blockIdx.z;
    const int x0 = blockIdx.x * 32;
    const int y0 = blockIdx.y * TH;
    const int tx = threadIdx.x;
    const int ty = threadIdx.y;
    const int tid = ty * 32 + tx;

    // s_w[(ci*9+tap)*COUT + co] = wt[(co*CIN+ci)*9 + tap]
    for (int i = tid; i < CIN * 9 * COUT; i += 128) {
        int co = i % COUT;
        int r  = i / COUT;
        int ci = r / 9, tap = r % 9;
        s_w[i] = wt[(co * CIN + ci) * 9 + tap];
    }

    ull acc[ROWS][COUT / 2];
#pragma unroll
    for (int k = 0; k < ROWS; k++)
#pragma unroll
        for (int j = 0; j < COUT / 2; j++) acc[k][j] = 0ull;

    const float* inb = in + (size_t)b * CIN * NPIX;

    for (int cch0 = 0; cch0 < CIN; cch0 += CCH) {
        __syncthreads();
        for (int i = tid; i < CCH * HR * 34; i += 128) {
            int ci = i / (HR * 34);
            int rr = (i / 34) % HR;
            int cc = i % 34;
            int gy = y0 + rr - 1, gx = x0 + cc - 1;
            float v = 0.0f;
            if ((unsigned)gy < 256u && (unsigned)gx < 256u) {
                v = inb[(size_t)(cch0 + ci) * NPIX + gy * 256 + gx];
                if (RELU) v = fmaxf(v, 0.0f);
            }
            s_in[ci][rr][cc] = v;
        }
        __syncthreads();

#pragma unroll 1
        for (int cl = 0; cl < CCH; ++cl) {
            ull pv[ROWS + 2][3];
#pragma unroll
            for (int rr = 0; rr < ROWS + 2; rr++)
#pragma unroll
                for (int c = 0; c < 3; c++) {
                    float vv = s_in[cl][ty * ROWS + rr][tx + c];
                    pv[rr][c] = pack2(vv, vv);
                }

            const float* wp = s_w + (size_t)(cch0 + cl) * 9 * COUT;
#pragma unroll
            for (int ky = 0; ky < 3; ky++)
#pragma unroll
                for (int kx = 0; kx < 3; kx++) {
                    const ull* w2 = (const ull*)(wp + (ky * 3 + kx) * COUT);
#pragma unroll
                    for (int j = 0; j < COUT / 2; j++) {
                        ull w = w2[j];
#pragma unroll
                        for (int r = 0; r < ROWS; r++)
                            fma2(acc[r][j], pv[ky + r][kx], w);
                    }
                }
        }
    }

    float* outb = out + (size_t)b * COUT * NPIX;
#pragma unroll
    for (int r = 0; r < ROWS; r++) {
        const int y = y0 + ty * ROWS + r;
#pragma unroll
        for (int j = 0; j < COUT / 2; j++) {
            float a, bb;
            unpack2(acc[r][j], a, bb);
            outb[(size_t)(2 * j)     * NPIX + y * 256 + x0 + tx] = a;
            outb[(size_t)(2 * j + 1) * NPIX + y * 256 + x0 + tx] = bb;
        }
    }
}

__global__ void __launch_bounds__(128) k_conv1(const float* __restrict__ x,
                                               const float* __restrict__ w) {
    conv_body<9, 10, 9, 4, true>(x, w, g_p1);
}
__global__ void __launch_bounds__(128) k_conv2(const float* __restrict__ w) {
    conv_body<10, 20, 10, 4, true>(g_p1, w, g_p2);
}
__global__ void __launch_bounds__(128) k_conv3(const float* __restrict__ w) {
    conv_body<20, 54, 5, 2, false>(g_p2, w, g_p3);
}

// ---------------------------------------------------------------------------
// kappa/m outputs + KG/M1/M2 grids.
//   out_kap flat = sp10(p3 ch 0..8)   (dense elementwise, float4)
//   out_m   flat = copy (p3 ch 9..26) (dense, float4)
//   grids: value at [b,t,n] = block_flat[n*9+t]  (smem transpose, no amp.)
// ---------------------------------------------------------------------------
__global__ void __launch_bounds__(256) k_build_kgm(float* __restrict__ out_kap,
                                                   float* __restrict__ out_m) {
    __shared__ float sk[2304], s1[2304], s2[2304];
    const int blk = blockIdx.x;
    const int b  = blk >> 8;
    const int n0 = (blk & 255) * 256;
    const int tid = threadIdx.x;

    const float4* pk  = (const float4*)(g_p3 + (size_t)b * 54 * NPIX + (size_t)n0 * 9);
    const float4* pm1 = (const float4*)(g_p3 + (size_t)b * 54 * NPIX + (size_t)9  * NPIX + (size_t)n0 * 9);
    const float4* pm2 = (const float4*)(g_p3 + (size_t)b * 54 * NPIX + (size_t)18 * NPIX + (size_t)n0 * 9);
    for (int i = tid; i < 576; i += 256) {
        ((float4*)sk)[i] = pk[i];
        ((float4*)s1)[i] = pm1[i];
        ((float4*)s2)[i] = pm2[i];
    }
    __syncthreads();

    const int n = n0 + tid;
    const size_t gb = (size_t)b * NT * NPIX + n;
#pragma unroll
    for (int t = 0; t < 9; t++) {
        float kv = sp10(sk[tid * 9 + t]);
        sk[tid * 9 + t] = kv;
        g_KG[gb + (size_t)t * NPIX] = kv;
        g_M1[gb + (size_t)t * NPIX] = s1[tid * 9 + t];
        g_M2[gb + (size_t)t * NPIX] = s2[tid * 9 + t];
    }
    __syncthreads();

    float4* ok  = (float4*)(out_kap + (size_t)b * 9 * NPIX + (size_t)n0 * 9);
    float4* om1 = (float4*)(out_m + (size_t)b * 18 * NPIX + (size_t)n0 * 9);
    float4* om2 = (float4*)(out_m + (size_t)b * 18 * NPIX + (size_t)9 * NPIX + (size_t)n0 * 9);
    for (int i = tid; i < 576; i += 256) {
        ok[i]  = ((float4*)sk)[i];
        om1[i] = ((float4*)s1)[i];
        om2[i] = ((float4*)s2)[i];
    }
}

// ---------------------------------------------------------------------------
// H output (smem-staged dense stores) + H11/HB/H22 grids (coalesced).
// ---------------------------------------------------------------------------
__global__ void __launch_bounds__(256) k_build_H(float* __restrict__ out_H) {
    __shared__ float s00[2304], s01[2304], s11[2304];
    const int blk = blockIdx.x;
    const int b  = blk >> 8;
    const int n0 = (blk & 255) * 256;
    const int tid = threadIdx.x;
    const int n = n0 + tid;

    const float* pb = g_p3 + (size_t)b * 54 * NPIX;
    const size_t gb = (size_t)b * NT * NPIX + n;
#pragma unroll
    for (int t = 0; t < 9; t++) {
        float gg = sp10(pb[(size_t)(27 + t) * NPIX + n]);
        float vx = pb[(size_t)(36 + t) * NPIX + n];
        float vy = pb[(size_t)(45 + t) * NPIX + n];
        float a  = gg + vx * vx;
        float cd = vx * vy;
        float d2 = gg + vy * vy;
        s00[tid * 9 + t] = a;
        s01[tid * 9 + t] = cd;
        s11[tid * 9 + t] = d2;
        size_t gi = gb + (size_t)t * NPIX;
        g_H11[gi] = a;
        g_HB [gi] = 2.0f * cd;
        g_H22[gi] = d2;
    }
    __syncthreads();

    float4* h00 = (float4*)(out_H + ((size_t)(b * 4 + 0)) * 9 * NPIX + (size_t)n0 * 9);
    float4* h01 = (float4*)(out_H + ((size_t)(b * 4 + 1)) * 9 * NPIX + (size_t)n0 * 9);
    float4* h10 = (float4*)(out_H + ((size_t)(b * 4 + 2)) * 9 * NPIX + (size_t)n0 * 9);
    float4* h11 = (float4*)(out_H + ((size_t)(b * 4 + 3)) * 9 * NPIX + (size_t)n0 * 9);
    for (int i = tid; i < 576; i += 256) {
        float4 v01 = ((float4*)s01)[i];
        h00[i] = ((float4*)s00)[i];
        h01[i] = v01;
        h10[i] = v01;
        h11[i] = ((float4*)s11)[i];
    }
}

// ---------------------------------------------------------------------------
// Fused stencil: per (b, 32x32 tile), loop t = 0..8:
//   load xg(t) (transposed read of x, 36x36 halo), coeffs(t) (34x34),
//   compute w(t)=M(xg) on 34x34 in smem (zero outside domain),
//   compute v(t)=M(w) on 32x32, accumulate
//     x_out = sum_t [ xg_t*v_t + 1_{1..7} xg_t^2 ] - sum_k w_k*(xg_{k-1}+xg_{k+1})
//   with rotating per-thread registers (xg prev / w prev centers).
// ---------------------------------------------------------------------------
__device__ __forceinline__ float stencil_A(float u, float xpv, float xmv,
                                           float ypv, float ymv,
                                           float pp, float pm, float mp, float mm,
                                           float kap, float m1, float m2,
                                           float h11, float hb, float h22) {
    return kap * kap * u
         + m1 * 0.5f * (xpv - xmv)
         + m2 * 0.5f * (ypv - ymv)
         - (h11 * (xpv - 2.0f * u + xmv)
            + hb * 0.25f * ((pp - pm) - (mp - mm))
            + h22 * (ypv - 2.0f * u + ymv));
}

__global__ void __launch_bounds__(256) k_stencil(const float* __restrict__ x) {
    __shared__ float s_xg[36][37];
    __shared__ float s_co[6][34][35];
    __shared__ float s_w[34][36];
    __shared__ float s_red[8];

    const int b  = blockIdx.z;
    const int a0 = blockIdx.y * 32;
    const int c0 = blockIdx.x * 32;
    const int tid = threadIdx.x;

    float xgp[4], wprev[4];
#pragma unroll
    for (int j = 0; j < 4; j++) { xgp[j] = 0.0f; wprev[j] = 0.0f; }
    float acc = 0.0f;

    for (int t = 0; t < 9; t++) {
        __syncthreads();
        const float* xp = x + (size_t)(b * 9 + t) * NPIX;
        // xg(ga,gc) = x_plane[gc*256+ga]; coalesced along ga.
        for (int i = tid; i < 1296; i += 256) {
            int xr = i / 36, xc = i - xr * 36;      // xr: c-offset, xc: a-offset
            int gc = c0 - 2 + xr, ga = a0 - 2 + xc;
            float v = 0.0f;
            if ((unsigned)gc < 256u && (unsigned)ga < 256u)
                v = xp[gc * 256 + ga];
            s_xg[xc][xr] = v;
        }
        const size_t pbase = (size_t)(b * 9 + t) * NPIX;
        for (int i = tid; i < 1156; i += 256) {
            int r = i / 34, c = i - r * 34;
            int ga = a0 - 1 + r, gc = c0 - 1 + c;
            bool ok = ((unsigned)ga < 256u) && ((unsigned)gc < 256u);
            size_t idx = pbase + (size_t)ga * 256 + gc;
            s_co[0][r][c] = ok ? g_KG [idx] : 0.0f;
            s_co[1][r][c] = ok ? g_M1 [idx] : 0.0f;
            s_co[2][r][c] = ok ? g_M2 [idx] : 0.0f;
            s_co[3][r][c] = ok ? g_H11[idx] : 0.0f;
            s_co[4][r][c] = ok ? g_HB [idx] : 0.0f;
            s_co[5][r][c] = ok ? g_H22[idx] : 0.0f;
        }
        __syncthreads();

        // w = M(xg) on 34x34 halo region; zero outside the true domain.
        for (int i = tid; i < 1156; i += 256) {
            int r = i / 34, c = i - r * 34;
            int ga = a0 - 1 + r, gc = c0 - 1 + c;
            float w = 0.0f;
            if ((unsigned)ga < 256u && (unsigned)gc < 256u) {
                float u   = s_xg[r + 1][c + 1];
                float xpv = s_xg[r + 2][c + 1], xmv = s_xg[r][c + 1];
                float ypv = s_xg[r + 1][c + 2], ymv = s_xg[r + 1][c];
                float pp  = s_xg[r + 2][c + 2], pm  = s_xg[r + 2][c];
                float mp  = s_xg[r][c + 2],     mm  = s_xg[r][c];
                w = u + stencil_A(u, xpv, xmv, ypv, ymv, pp, pm, mp, mm,
                                  s_co[0][r][c], s_co[1][r][c], s_co[2][r][c],
                                  s_co[3][r][c], s_co[4][r][c], s_co[5][r][c]);
            }
            s_w[r][c] = w;
        }
        __syncthreads();

        // v = M(w) on 32x32 interior; accumulate.
#pragma unroll
        for (int j = 0; j < 4; j++) {
            int p = tid + j * 256;
            int r = p >> 5, c = p & 31;
            float u   = s_w[r + 1][c + 1];
            float xpv = s_w[r + 2][c + 1], xmv = s_w[r][c + 1];
            float ypv = s_w[r + 1][c + 2], ymv = s_w[r + 1][c];
            float pp  = s_w[r + 2][c + 2], pm  = s_w[r + 2][c];
            float mp  = s_w[r][c + 2],     mm  = s_w[r][c];
            float v = u + stencil_A(u, xpv, xmv, ypv, ymv, pp, pm, mp, mm,
                                    s_co[0][r + 1][c + 1], s_co[1][r + 1][c + 1],
                                    s_co[2][r + 1][c + 1], s_co[3][r + 1][c + 1],
                                    s_co[4][r + 1][c + 1], s_co[5][r + 1][c + 1]);
            float xgc = s_xg[r + 2][c + 2];
            acc += xgc * v;
            if (t >= 1 && t <= 7) acc += xgc * xgc;
            if (t >= 1) acc -= u * xgp[j] + wprev[j] * xgc;
            xgp[j]   = xgc;
            wprev[j] = u;
        }
    }

#pragma unroll
    for (int o = 16; o > 0; o >>= 1)
        acc += __shfl_down_sync(0xffffffffu, acc, o);
    if ((tid & 31) == 0) s_red[tid >> 5] = acc;
    __syncthreads();
    if (tid == 0) {
        float s = 0.0f;
#pragma unroll
        for (int i = 0; i < 8; i++) s += s_red[i];
        g_part[b * 64 + blockIdx.y * 8 + blockIdx.x] = s;
    }
}

// Deterministic per-batch reduction of 64 tile partials.
__global__ void __launch_bounds__(64) k_final(float* __restrict__ out_x) {
    __shared__ float s[2];
    int b = blockIdx.x, tid = threadIdx.x;
    float v = g_part[b * 64 + tid];
#pragma unroll
    for (int o = 16; o > 0; o >>= 1)
        v += __shfl_down_sync(0xffffffffu, v, o);
    if ((tid & 31) == 0) s[tid >> 5] = v;
    __syncthreads();
    if (tid == 0) out_x[b] = s[0] + s[1];
}

// ---------------------------------------------------------------------------
// Launch. Output layout: [x_out(16)] [kappa_r 16*9*65536] [m_r 16*18*65536]
//                        [H_r 16*4*65536*9]
// ---------------------------------------------------------------------------
extern "C" void kernel_launch(void* const* d_in, const int* in_sizes, int n_in,
                              void* d_out, int out_size) {
    (void)in_sizes; (void)n_in; (void)out_size;
    const float* x  = (const float*)d_in[0];
    const float* w1 = (const float*)d_in[4];
    const float* w2 = (const float*)d_in[5];
    const float* w3 = (const float*)d_in[6];

    float* out     = (float*)d_out;
    float* out_kap = out + 16;
    float* out_m   = out + 16 + (size_t)NB * 9 * NPIX;
    float* out_H   = out + 16 + (size_t)NB * 9 * NPIX + (size_t)NB * 18 * NPIX;

    dim3 cb(32, 4);
    k_conv1<<<dim3(8, 16, NB), cb>>>(x, w1);
    k_conv2<<<dim3(8, 16, NB), cb>>>(w2);
    k_conv3<<<dim3(8, 32, NB), cb>>>(w3);

    k_build_kgm<<<4096, 256>>>(out_kap, out_m);
    k_build_H  <<<4096, 256>>>(out_H);

    k_stencil<<<dim3(8, 8, NB), 256>>>(x);
    k_final  <<<NB, 64>>>(out);
}

// round 9
// speedup vs baseline: 1.3587x; 1.0458x over previous
#include <cuda_runtime.h>
#include <cstdint>

#define NT   9
#define NPIX 65536
#define NB   16

typedef unsigned long long ull;

// ---------------------------------------------------------------------------
// Packed f32x2 helpers (Blackwell fma.rn.f32x2, PTX-only)
// ---------------------------------------------------------------------------
__device__ __forceinline__ ull pack2(float a, float b) {
    ull r;
    asm("mov.b64 %0, {%1,%2};" : "=l"(r) : "f"(a), "f"(b));
    return r;
}
__device__ __forceinline__ void unpack2(ull v, float& a, float& b) {
    asm("mov.b64 {%0,%1}, %2;" : "=f"(a), "=f"(b) : "l"(v));
}
__device__ __forceinline__ void fma2(ull& acc, ull v, ull w) {
    asm("fma.rn.f32x2 %0, %1, %2, %3;" : "=l"(acc) : "l"(v), "l"(w), "l"(acc));
}

__device__ __forceinline__ float sp10(float x) {
    float z = 10.0f * x;
    return fmaxf(x, 0.0f) + 0.1f * log1pf(expf(-fabsf(z)));
}

// ---------------------------------------------------------------------------
// Scratch (device globals — allocation-free)
// ---------------------------------------------------------------------------
__device__ float g_p1[(size_t)NB * 10 * NPIX];
__device__ float g_p2[(size_t)NB * 20 * NPIX];
__device__ float g_KG [(size_t)NB * NT * NPIX];
__device__ float g_M1 [(size_t)NB * NT * NPIX];
__device__ float g_M2 [(size_t)NB * NT * NPIX];
__device__ float g_H11[(size_t)NB * NT * NPIX];
__device__ float g_HB [(size_t)NB * NT * NPIX];
__device__ float g_H22[(size_t)NB * NT * NPIX];
__device__ float g_part[NB * 64];

// ---------------------------------------------------------------------------
// Direct 3x3 SAME conv (conv1 / conv2), NCHW/OIHW, zero pad.
// ---------------------------------------------------------------------------
template <int CIN, int COUT, int CCH, int ROWS, bool RELU>
__device__ __forceinline__ void conv_body(const float* __restrict__ in,
                                          const float* __restrict__ wt,
                                          float* __restrict__ out) {
    constexpr int TH = 4 * ROWS;
    constexpr int HR = TH + 2;
    __shared__ __align__(16) float s_w[CIN * 9 * COUT];
    __shared__ float s_in[CCH][HR][34];

    const int b  = blockIdx.z;
    const int x0 = blockIdx.x * 32;
    const int y0 = blockIdx.y * TH;
    const int tx = threadIdx.x;
    const int ty = threadIdx.y;
    const int tid = ty * 32 + tx;

    for (int i = tid; i < CIN * 9 * COUT; i += 128) {
        int co = i % COUT;
        int r  = i / COUT;
        int ci = r / 9, tap = r % 9;
        s_w[i] = wt[(co * CIN + ci) * 9 + tap];
    }

    ull acc[ROWS][COUT / 2];
#pragma unroll
    for (int k = 0; k < ROWS; k++)
#pragma unroll
        for (int j = 0; j < COUT / 2; j++) acc[k][j] = 0ull;

    const float* inb = in + (size_t)b * CIN * NPIX;

    for (int cch0 = 0; cch0 < CIN; cch0 += CCH) {
        __syncthreads();
        for (int i = tid; i < CCH * HR * 34; i += 128) {
            int ci = i / (HR * 34);
            int rr = (i / 34) % HR;
            int cc = i % 34;
            int gy = y0 + rr - 1, gx = x0 + cc - 1;
            float v = 0.0f;
            if ((unsigned)gy < 256u && (unsigned)gx < 256u) {
                v = inb[(size_t)(cch0 + ci) * NPIX + gy * 256 + gx];
                if (RELU) v = fmaxf(v, 0.0f);
            }
            s_in[ci][rr][cc] = v;
        }
        __syncthreads();

#pragma unroll 1
        for (int cl = 0; cl < CCH; ++cl) {
            ull pv[ROWS + 2][3];
#pragma unroll
            for (int rr = 0; rr < ROWS + 2; rr++)
#pragma unroll
                for (int c = 0; c < 3; c++) {
                    float vv = s_in[cl][ty * ROWS + rr][tx + c];
                    pv[rr][c] = pack2(vv, vv);
                }

            const float* wp = s_w + (size_t)(cch0 + cl) * 9 * COUT;
#pragma unroll
            for (int ky = 0; ky < 3; ky++)
#pragma unroll
                for (int kx = 0; kx < 3; kx++) {
                    const ull* w2 = (const ull*)(wp + (ky * 3 + kx) * COUT);
#pragma unroll
                    for (int j = 0; j < COUT / 2; j++) {
                        ull w = w2[j];
#pragma unroll
                        for (int r = 0; r < ROWS; r++)
                            fma2(acc[r][j], pv[ky + r][kx], w);
                    }
                }
        }
    }

    float* outb = out + (size_t)b * COUT * NPIX;
#pragma unroll
    for (int r = 0; r < ROWS; r++) {
        const int y = y0 + ty * ROWS + r;
#pragma unroll
        for (int j = 0; j < COUT / 2; j++) {
            float a, bb;
            unpack2(acc[r][j], a, bb);
            outb[(size_t)(2 * j)     * NPIX + y * 256 + x0 + tx] = a;
            outb[(size_t)(2 * j + 1) * NPIX + y * 256 + x0 + tx] = bb;
        }
    }
}

__global__ void __launch_bounds__(128) k_conv1(const float* __restrict__ x,
                                               const float* __restrict__ w) {
    conv_body<9, 10, 9, 4, true>(x, w, g_p1);
}
__global__ void __launch_bounds__(128) k_conv2(const float* __restrict__ w) {
    conv_body<10, 20, 10, 4, true>(g_p1, w, g_p2);
}

// ---------------------------------------------------------------------------
// conv3 FUSED (corrected):
//  - kappa/m flat outputs are RAW reshapes -> elementwise in PLANE layout:
//      out_kap[b, ch, y, x] = sp10(conv ch)   (ch 0..8)
//      out_m  [b, ch-9, y, x] = conv ch       (ch 9..26)
//    -> direct coalesced stores from registers.
//  - H flat output goes through a true transpose -> per-pixel n*9+t layout,
//    tile-local: smem-staged dense float4 stores.  H grids are PLANE data.
//  - KG/M1/M2 grids are the scrambled flat reinterpretation -> NOT tile-local;
//    produced by k_gridkgm afterwards from out_kap/out_m.
// ---------------------------------------------------------------------------
__global__ void __launch_bounds__(128) k_conv3f(const float* __restrict__ wt,
                                                float* __restrict__ out_kap,
                                                float* __restrict__ out_m,
                                                float* __restrict__ out_H) {
    constexpr int CIN = 20, COUT = 54, CCH = 5, ROWS = 2;
    constexpr int TH = 8, HR = 10;
    __shared__ __align__(16) float s_w[CIN * 9 * COUT];     // 38880 B
    __shared__ float s_in[CCH][HR][34];

    const int b  = blockIdx.z;
    const int x0 = blockIdx.x * 32;
    const int y0 = blockIdx.y * TH;
    const int tx = threadIdx.x;
    const int ty = threadIdx.y;
    const int tid = ty * 32 + tx;

    for (int i = tid; i < CIN * 9 * COUT; i += 128) {
        int co = i % COUT;
        int r  = i / COUT;
        int ci = r / 9, tap = r % 9;
        s_w[i] = wt[(co * CIN + ci) * 9 + tap];
    }

    ull acc[ROWS][COUT / 2];
#pragma unroll
    for (int k = 0; k < ROWS; k++)
#pragma unroll
        for (int j = 0; j < COUT / 2; j++) acc[k][j] = 0ull;

    const float* inb = g_p2 + (size_t)b * CIN * NPIX;

    for (int cch0 = 0; cch0 < CIN; cch0 += CCH) {
        __syncthreads();
        for (int i = tid; i < CCH * HR * 34; i += 128) {
            int ci = i / (HR * 34);
            int rr = (i / 34) % HR;
            int cc = i % 34;
            int gy = y0 + rr - 1, gx = x0 + cc - 1;
            float v = 0.0f;
            if ((unsigned)gy < 256u && (unsigned)gx < 256u)
                v = inb[(size_t)(cch0 + ci) * NPIX + gy * 256 + gx];
            s_in[ci][rr][cc] = v;
        }
        __syncthreads();

#pragma unroll 1
        for (int cl = 0; cl < CCH; ++cl) {
            ull pv[ROWS + 2][3];
#pragma unroll
            for (int rr = 0; rr < ROWS + 2; rr++)
#pragma unroll
                for (int c = 0; c < 3; c++) {
                    float vv = s_in[cl][ty * ROWS + rr][tx + c];
                    pv[rr][c] = pack2(vv, vv);
                }

            const float* wp = s_w + (size_t)(cch0 + cl) * 9 * COUT;
#pragma unroll
            for (int ky = 0; ky < 3; ky++)
#pragma unroll
                for (int kx = 0; kx < 3; kx++) {
                    const ull* w2 = (const ull*)(wp + (ky * 3 + kx) * COUT);
#pragma unroll
                    for (int j = 0; j < COUT / 2; j++) {
                        ull w = w2[j];
#pragma unroll
                        for (int r = 0; r < ROWS; r++)
                            fma2(acc[r][j], pv[ky + r][kx], w);
                    }
                }
        }
    }

    // ---- epilogue ------------------------------------------------------
    __syncthreads();                 // all warps done with s_w / s_in
    float* sf = s_w;                 // H staging: 3 * 2304 floats

    const size_t pb   = (size_t)b * NT * NPIX;
    const size_t pix0 = (size_t)(y0 + ty * ROWS) * 256 + (x0 + tx);
    float* okb = out_kap + (size_t)b * 9 * NPIX;
    float* omb = out_m   + (size_t)b * 18 * NPIX;

    float vh[ROWS][27];              // channels 27..53 per row

#pragma unroll
    for (int r = 0; r < ROWS; r++) {
        const size_t pix = pix0 + (size_t)r * 256;
        // pairs 0..12 -> channels 0..25 (kappa planes 0..8, m planes 0..16)
#pragma unroll
        for (int j = 0; j < 13; j++) {
            float lo, hi;
            unpack2(acc[r][j], lo, hi);
            const int c0 = 2 * j, c1 = 2 * j + 1;
            if (c0 < 9) okb[(size_t)c0 * NPIX + pix] = sp10(lo);
            else        omb[(size_t)(c0 - 9) * NPIX + pix] = lo;
            if (c1 < 9) okb[(size_t)c1 * NPIX + pix] = sp10(hi);
            else        omb[(size_t)(c1 - 9) * NPIX + pix] = hi;
        }
        // pair 13 -> ch 26 (m plane 17) and ch 27 (gamma t=0)
        {
            float lo, hi;
            unpack2(acc[r][13], lo, hi);
            omb[(size_t)17 * NPIX + pix] = lo;
            vh[r][0] = hi;
        }
        // pairs 14..26 -> channels 28..53
#pragma unroll
        for (int j = 14; j < 27; j++) {
            float lo, hi;
            unpack2(acc[r][j], lo, hi);
            vh[r][2 * j - 27] = lo;
            vh[r][2 * j - 26] = hi;
        }
    }

    // H: planes (coalesced) + stage flat (n*9+t layout)
#pragma unroll
    for (int r = 0; r < ROWS; r++) {
        const size_t pix = pix0 + (size_t)r * 256;
        float* st = sf + (size_t)(ty * ROWS + r) * 288 + tx * 9;
#pragma unroll
        for (int t = 0; t < 9; t++) {
            float gsp = sp10(vh[r][t]);
            float vx  = vh[r][9 + t];
            float vy  = vh[r][18 + t];
            float h00 = gsp + vx * vx;
            float cd  = vx * vy;
            float h11 = gsp + vy * vy;
            g_H11[pb + (size_t)t * NPIX + pix] = h00;
            g_HB [pb + (size_t)t * NPIX + pix] = 2.0f * cd;
            g_H22[pb + (size_t)t * NPIX + pix] = h11;
            st[t]            = h00;
            st[2304 + t]     = cd;
            st[2 * 2304 + t] = h11;
        }
    }
    __syncthreads();
    {
        float4* d00 = (float4*)(out_H + (size_t)(b * 4 + 0) * 9 * NPIX);
        float4* d01 = (float4*)(out_H + (size_t)(b * 4 + 1) * 9 * NPIX);
        float4* d10 = (float4*)(out_H + (size_t)(b * 4 + 2) * 9 * NPIX);
        float4* d11 = (float4*)(out_H + (size_t)(b * 4 + 3) * 9 * NPIX);
        const int xo4 = x0 * 9 / 4;   // x0 multiple of 32 -> exact
        for (int i = tid; i < 576; i += 128) {
            int row = i / 72, jj = i - row * 72;
            size_t o4 = (size_t)(y0 + row) * 576 + xo4 + jj;
            int s4 = row * 72 + jj;
            float4 cd4 = ((float4*)(sf + 2304))[s4];
            d00[o4] = ((float4*)sf)[s4];
            d01[o4] = cd4;
            d10[o4] = cd4;
            d11[o4] = ((float4*)(sf + 2 * 2304))[s4];
        }
    }
}

// ---------------------------------------------------------------------------
// KG/M1/M2 grids from the flat outputs (scrambled reinterpretation):
//   g_KG[b,t,n] = out_kap_flat[b, n*9+t]  (sp10 already applied)
// Dense float4 reads; stride-9 smem transpose (gcd(9,32)=1, conflict-free).
// ---------------------------------------------------------------------------
__global__ void __launch_bounds__(256) k_gridkgm(const float* __restrict__ ok,
                                                 const float* __restrict__ om) {
    __shared__ float sk[2304], s1[2304], s2[2304];
    const int blk = blockIdx.x;
    const int b  = blk >> 8;
    const int n0 = (blk & 255) * 256;
    const int tid = threadIdx.x;

    const float4* pk  = (const float4*)(ok + (size_t)b * 9 * NPIX + (size_t)n0 * 9);
    const float4* pm1 = (const float4*)(om + (size_t)b * 18 * NPIX + (size_t)n0 * 9);
    const float4* pm2 = (const float4*)(om + (size_t)b * 18 * NPIX + (size_t)9 * NPIX + (size_t)n0 * 9);
    for (int i = tid; i < 576; i += 256) {
        ((float4*)sk)[i] = pk[i];
        ((float4*)s1)[i] = pm1[i];
        ((float4*)s2)[i] = pm2[i];
    }
    __syncthreads();

    const int n = n0 + tid;
    const size_t gb = (size_t)b * NT * NPIX + n;
#pragma unroll
    for (int t = 0; t < 9; t++) {
        g_KG[gb + (size_t)t * NPIX] = sk[tid * 9 + t];
        g_M1[gb + (size_t)t * NPIX] = s1[tid * 9 + t];
        g_M2[gb + (size_t)t * NPIX] = s2[tid * 9 + t];
    }
}

// ---------------------------------------------------------------------------
// Fused stencil (unchanged): w = M(xg) on 34x34 halo, v = M(w) on 32x32,
// accumulate x_out terms with rotating registers.
// ---------------------------------------------------------------------------
__device__ __forceinline__ float stencil_A(float u, float xpv, float xmv,
                                           float ypv, float ymv,
                                           float pp, float pm, float mp, float mm,
                                           float kap, float m1, float m2,
                                           float h11, float hb, float h22) {
    return kap * kap * u
         + m1 * 0.5f * (xpv - xmv)
         + m2 * 0.5f * (ypv - ymv)
         - (h11 * (xpv - 2.0f * u + xmv)
            + hb * 0.25f * ((pp - pm) - (mp - mm))
            + h22 * (ypv - 2.0f * u + ymv));
}

__global__ void __launch_bounds__(256) k_stencil(const float* __restrict__ x) {
    __shared__ float s_xg[36][37];
    __shared__ float s_co[6][34][35];
    __shared__ float s_w[34][36];
    __shared__ float s_red[8];

    const int b  = blockIdx.z;
    const int a0 = blockIdx.y * 32;
    const int c0 = blockIdx.x * 32;
    const int tid = threadIdx.x;

    float xgp[4], wprev[4];
#pragma unroll
    for (int j = 0; j < 4; j++) { xgp[j] = 0.0f; wprev[j] = 0.0f; }
    float acc = 0.0f;

    for (int t = 0; t < 9; t++) {
        __syncthreads();
        const float* xp = x + (size_t)(b * 9 + t) * NPIX;
        for (int i = tid; i < 1296; i += 256) {
            int xr = i / 36, xc = i - xr * 36;
            int gc = c0 - 2 + xr, ga = a0 - 2 + xc;
            float v = 0.0f;
            if ((unsigned)gc < 256u && (unsigned)ga < 256u)
                v = xp[gc * 256 + ga];
            s_xg[xc][xr] = v;
        }
        const size_t pbase = (size_t)(b * 9 + t) * NPIX;
        for (int i = tid; i < 1156; i += 256) {
            int r = i / 34, c = i - r * 34;
            int ga = a0 - 1 + r, gc = c0 - 1 + c;
            bool ok = ((unsigned)ga < 256u) && ((unsigned)gc < 256u);
            size_t idx = pbase + (size_t)ga * 256 + gc;
            s_co[0][r][c] = ok ? g_KG [idx] : 0.0f;
            s_co[1][r][c] = ok ? g_M1 [idx] : 0.0f;
            s_co[2][r][c] = ok ? g_M2 [idx] : 0.0f;
            s_co[3][r][c] = ok ? g_H11[idx] : 0.0f;
            s_co[4][r][c] = ok ? g_HB [idx] : 0.0f;
            s_co[5][r][c] = ok ? g_H22[idx] : 0.0f;
        }
        __syncthreads();

        for (int i = tid; i < 1156; i += 256) {
            int r = i / 34, c = i - r * 34;
            int ga = a0 - 1 + r, gc = c0 - 1 + c;
            float w = 0.0f;
            if ((unsigned)ga < 256u && (unsigned)gc < 256u) {
                float u   = s_xg[r + 1][c + 1];
                float xpv = s_xg[r + 2][c + 1], xmv = s_xg[r][c + 1];
                float ypv = s_xg[r + 1][c + 2], ymv = s_xg[r + 1][c];
                float pp  = s_xg[r + 2][c + 2], pm  = s_xg[r + 2][c];
                float mp  = s_xg[r][c + 2],     mm  = s_xg[r][c];
                w = u + stencil_A(u, xpv, xmv, ypv, ymv, pp, pm, mp, mm,
                                  s_co[0][r][c], s_co[1][r][c], s_co[2][r][c],
                                  s_co[3][r][c], s_co[4][r][c], s_co[5][r][c]);
            }
            s_w[r][c] = w;
        }
        __syncthreads();

#pragma unroll
        for (int j = 0; j < 4; j++) {
            int p = tid + j * 256;
            int r = p >> 5, c = p & 31;
            float u   = s_w[r + 1][c + 1];
            float xpv = s_w[r + 2][c + 1], xmv = s_w[r][c + 1];
            float ypv = s_w[r + 1][c + 2], ymv = s_w[r + 1][c];
            float pp  = s_w[r + 2][c + 2], pm  = s_w[r + 2][c];
            float mp  = s_w[r][c + 2],     mm  = s_w[r][c];
            float v = u + stencil_A(u, xpv, xmv, ypv, ymv, pp, pm, mp, mm,
                                    s_co[0][r + 1][c + 1], s_co[1][r + 1][c + 1],
                                    s_co[2][r + 1][c + 1], s_co[3][r + 1][c + 1],
                                    s_co[4][r + 1][c + 1], s_co[5][r + 1][c + 1]);
            float xgc = s_xg[r + 2][c + 2];
            acc += xgc * v;
            if (t >= 1 && t <= 7) acc += xgc * xgc;
            if (t >= 1) acc -= u * xgp[j] + wprev[j] * xgc;
            xgp[j]   = xgc;
            wprev[j] = u;
        }
    }

#pragma unroll
    for (int o = 16; o > 0; o >>= 1)
        acc += __shfl_down_sync(0xffffffffu, acc, o);
    if ((tid & 31) == 0) s_red[tid >> 5] = acc;
    __syncthreads();
    if (tid == 0) {
        float s = 0.0f;
#pragma unroll
        for (int i = 0; i < 8; i++) s += s_red[i];
        g_part[b * 64 + blockIdx.y * 8 + blockIdx.x] = s;
    }
}

__global__ void __launch_bounds__(64) k_final(float* __restrict__ out_x) {
    __shared__ float s[2];
    int b = blockIdx.x, tid = threadIdx.x;
    float v = g_part[b * 64 + tid];
#pragma unroll
    for (int o = 16; o > 0; o >>= 1)
        v += __shfl_down_sync(0xffffffffu, v, o);
    if ((tid & 31) == 0) s[tid >> 5] = v;
    __syncthreads();
    if (tid == 0) out_x[b] = s[0] + s[1];
}

// ---------------------------------------------------------------------------
// Launch. Output: [x_out(16)] [kappa_r 16*9*65536] [m_r 16*18*65536]
//                 [H_r 16*4*9*65536]
// ---------------------------------------------------------------------------
extern "C" void kernel_launch(void* const* d_in, const int* in_sizes, int n_in,
                              void* d_out, int out_size) {
    (void)in_sizes; (void)n_in; (void)out_size;
    const float* x  = (const float*)d_in[0];
    const float* w1 = (const float*)d_in[4];
    const float* w2 = (const float*)d_in[5];
    const float* w3 = (const float*)d_in[6];

    float* out     = (float*)d_out;
    float* out_kap = out + 16;
    float* out_m   = out + 16 + (size_t)NB * 9 * NPIX;
    float* out_H   = out + 16 + (size_t)NB * 9 * NPIX + (size_t)NB * 18 * NPIX;

    dim3 cb(32, 4);
    k_conv1 <<<dim3(8, 16, NB), cb>>>(x, w1);
    k_conv2 <<<dim3(8, 16, NB), cb>>>(w2);
    k_conv3f<<<dim3(8, 32, NB), cb>>>(w3, out_kap, out_m, out_H);

    k_gridkgm<<<4096, 256>>>(out_kap, out_m);

    k_stencil<<<dim3(8, 8, NB), 256>>>(x);
    k_final  <<<NB, 64>>>(out);
}